// round 9
// baseline (speedup 1.0000x reference)
#include <cuda_runtime.h>
#include <cuda_bf16.h>
#include <stdint.h>
#include <math.h>

// Problem constants
#define TOK   8192
#define DIM   1024
#define HID   2048
#define NE    8
#define NPAIR (TOK * 2)

// ---------------------------------------------------------------------------
// Device scratch
// ---------------------------------------------------------------------------
__device__ int   g_counts[NE];
__device__ int   g_offs[NE];
__device__ int   g_ptoken[NE * TOK];
__device__ float g_pgate [NE * TOK];
__device__ float g_cgate [NPAIR];
__device__ int   g_tslot [NPAIR];

__device__ __nv_bfloat16 g_w1h[(size_t)NE * HID * DIM];
__device__ __nv_bfloat16 g_w1l[(size_t)NE * HID * DIM];
__device__ __nv_bfloat16 g_w3h[(size_t)NE * HID * DIM];
__device__ __nv_bfloat16 g_w3l[(size_t)NE * HID * DIM];
__device__ __nv_bfloat16 g_w2h[(size_t)NE * DIM * HID];
__device__ __nv_bfloat16 g_w2l[(size_t)NE * DIM * HID];

__device__ __nv_bfloat16 g_Xh[(size_t)NPAIR * DIM];
__device__ __nv_bfloat16 g_Xl[(size_t)NPAIR * DIM];
__device__ __nv_bfloat16 g_Gh[(size_t)NPAIR * HID];
__device__ __nv_bfloat16 g_Gl[(size_t)NPAIR * HID];
__device__ float         g_Y [(size_t)NPAIR * DIM];

// ---------------------------------------------------------------------------
// Helpers
// ---------------------------------------------------------------------------
__device__ __forceinline__ uint32_t smem_u32(const void* p) {
    uint32_t a;
    asm("{ .reg .u64 t; cvta.to.shared.u64 t, %1; cvt.u32.u64 %0, t; }"
        : "=r"(a) : "l"(p));
    return a;
}

#define CP_ASYNC16(dst, src, sz) \
    asm volatile("cp.async.cg.shared.global [%0], [%1], 16, %2;" \
                 :: "r"(dst), "l"(src), "r"(sz))
#define CP_COMMIT() asm volatile("cp.async.commit_group;")
#define CP_WAIT1()  asm volatile("cp.async.wait_group 1;")
#define CP_WAIT0()  asm volatile("cp.async.wait_group 0;")

__device__ __forceinline__ void ldsm4(uint32_t* r, uint32_t addr) {
    asm volatile("ldmatrix.sync.aligned.m8n8.x4.shared.b16 {%0,%1,%2,%3}, [%4];"
                 : "=r"(r[0]), "=r"(r[1]), "=r"(r[2]), "=r"(r[3]) : "r"(addr));
}

__device__ __forceinline__ void mma16816(float* c, const uint32_t* a, const uint32_t* b) {
    asm volatile(
        "mma.sync.aligned.m16n8k16.row.col.f32.bf16.bf16.f32 "
        "{%0,%1,%2,%3}, {%4,%5,%6,%7}, {%8,%9}, {%0,%1,%2,%3};"
        : "+f"(c[0]), "+f"(c[1]), "+f"(c[2]), "+f"(c[3])
        : "r"(a[0]), "r"(a[1]), "r"(a[2]), "r"(a[3]), "r"(b[0]), "r"(b[1]));
}

__device__ __forceinline__ void split_bf16(float v, __nv_bfloat16& h, __nv_bfloat16& l) {
    h = __float2bfloat16(v);
    l = __float2bfloat16(v - __bfloat162float(h));
}

// ---------------------------------------------------------------------------
// Stage 0: zero expert counters
// ---------------------------------------------------------------------------
__global__ void zero_counts_kernel() {
    if (threadIdx.x < NE) g_counts[threadIdx.x] = 0;
}

// ---------------------------------------------------------------------------
// Weight conversion fp32 -> bf16 hi/lo (all 3 matrices, one launch)
// ---------------------------------------------------------------------------
__global__ void convert_kernel(const float* __restrict__ w1,
                               const float* __restrict__ w2,
                               const float* __restrict__ w3, int n4) {
    int blk_per = n4 / 256;
    int which = blockIdx.x / blk_per;
    int i = (blockIdx.x - which * blk_per) * 256 + threadIdx.x;
    const float* s;
    __nv_bfloat16 *h, *l;
    if (which == 0)      { s = w1; h = g_w1h; l = g_w1l; }
    else if (which == 1) { s = w3; h = g_w3h; l = g_w3l; }
    else                 { s = w2; h = g_w2h; l = g_w2l; }
    float4 v = ((const float4*)s)[i];
    __nv_bfloat16 hx, lx, hy, ly, hz, lz, hw, lw;
    split_bf16(v.x, hx, lx); split_bf16(v.y, hy, ly);
    split_bf16(v.z, hz, lz); split_bf16(v.w, hw, lw);
    ((__nv_bfloat162*)h)[2 * i]     = __halves2bfloat162(hx, hy);
    ((__nv_bfloat162*)h)[2 * i + 1] = __halves2bfloat162(hz, hw);
    ((__nv_bfloat162*)l)[2 * i]     = __halves2bfloat162(lx, ly);
    ((__nv_bfloat162*)l)[2 * i + 1] = __halves2bfloat162(lz, lw);
}

// ---------------------------------------------------------------------------
// Stage 1: router (noisy top-2)
// ---------------------------------------------------------------------------
__global__ void router_kernel(const float* __restrict__ x,
                              const float* __restrict__ noise,
                              const float* __restrict__ rw,
                              const float* __restrict__ rb,
                              const float* __restrict__ nw,
                              const float* __restrict__ nb)
{
    int gwarp = (int)((blockIdx.x * blockDim.x + threadIdx.x) >> 5);
    int lane  = threadIdx.x & 31;
    if (gwarp >= TOK) return;
    const float* xr = x + (size_t)gwarp * DIM;

    float accR[NE], accN[NE];
#pragma unroll
    for (int e = 0; e < NE; e++) { accR[e] = 0.0f; accN[e] = 0.0f; }
    for (int i = lane; i < DIM; i += 32) {
        float xv = xr[i];
#pragma unroll
        for (int e = 0; e < NE; e++) {
            accR[e] = fmaf(xv, rw[e * DIM + i], accR[e]);
            accN[e] = fmaf(xv, nw[e * DIM + i], accN[e]);
        }
    }
#pragma unroll
    for (int e = 0; e < NE; e++) {
#pragma unroll
        for (int o = 16; o > 0; o >>= 1) {
            accR[e] += __shfl_xor_sync(0xffffffffu, accR[e], o);
            accN[e] += __shfl_xor_sync(0xffffffffu, accN[e], o);
        }
    }
    if (lane == 0) {
        float noisy[NE];
#pragma unroll
        for (int e = 0; e < NE; e++) {
            float lg = accR[e] + rb[e];
            float nl = accN[e] + nb[e];
            float sp = fmaxf(nl, 0.0f) + log1pf(expf(-fabsf(nl)));
            noisy[e] = lg + noise[(size_t)gwarp * NE + e] * sp;
        }
        int i1 = 0;
#pragma unroll
        for (int e = 1; e < NE; e++) if (noisy[e] > noisy[i1]) i1 = e;
        int i2 = (i1 == 0) ? 1 : 0;
#pragma unroll
        for (int e = 0; e < NE; e++) {
            if (e == i1 || e == i2) continue;
            if (noisy[e] > noisy[i2]) i2 = e;
        }
        float e2 = expf(noisy[i2] - noisy[i1]);
        float inv = 1.0f / (1.0f + e2);
        int s1 = atomicAdd(&g_counts[i1], 1);
        g_ptoken[i1 * TOK + s1] = gwarp;
        g_pgate [i1 * TOK + s1] = inv;
        int s2 = atomicAdd(&g_counts[i2], 1);
        g_ptoken[i2 * TOK + s2] = gwarp;
        g_pgate [i2 * TOK + s2] = e2 * inv;
        g_tslot[2 * gwarp]     = i1 * TOK + s1;
        g_tslot[2 * gwarp + 1] = i2 * TOK + s2;
    }
}

// ---------------------------------------------------------------------------
// Stage 2: prefix scan
// ---------------------------------------------------------------------------
__global__ void scan_offsets_kernel() {
    if (threadIdx.x == 0) {
        int s = 0;
#pragma unroll
        for (int e = 0; e < NE; e++) { g_offs[e] = s; s += g_counts[e]; }
    }
}

// ---------------------------------------------------------------------------
// Stage 3: gather + bf16 hi/lo split
// ---------------------------------------------------------------------------
__global__ void gather_kernel(const float* __restrict__ x) {
    int e    = blockIdx.x >> 13;
    int slot = blockIdx.x & (TOK - 1);
    if (slot >= g_counts[e]) return;
    int token = g_ptoken[e * TOK + slot];
    int p     = g_offs[e] + slot;

    float4 v = ((const float4*)(x + (size_t)token * DIM))[threadIdx.x];
    __nv_bfloat16 hx, lx, hy, ly, hz, lz, hw, lw;
    split_bf16(v.x, hx, lx); split_bf16(v.y, hy, ly);
    split_bf16(v.z, hz, lz); split_bf16(v.w, hw, lw);
    size_t o = (size_t)p * DIM + (size_t)threadIdx.x * 4;
    *(__nv_bfloat162*)&g_Xh[o]     = __halves2bfloat162(hx, hy);
    *(__nv_bfloat162*)&g_Xh[o + 2] = __halves2bfloat162(hz, hw);
    *(__nv_bfloat162*)&g_Xl[o]     = __halves2bfloat162(lx, ly);
    *(__nv_bfloat162*)&g_Xl[o + 2] = __halves2bfloat162(lz, lw);

    if (threadIdx.x == 0) g_cgate[p] = g_pgate[e * TOK + slot];
}

// ---------------------------------------------------------------------------
// GEMM tiling: 128x128 block tiles, BK=32, 512 threads (4x4 warps, 32x32/warp)
// padded smem rows: 64B payload + 16B pad = 80B pitch
// ---------------------------------------------------------------------------
#define ROWB     80
#define T_BYTES  (128 * ROWB)                 // 10240 per 128-row tile

#define G1_STAGE (6 * T_BYTES)                // Ah,Al,B1h,B1l,B3h,B3l = 61440
#define G1_SMEM  (3 * G1_STAGE)               // 184320 (3-stage)
#define G2_STAGE (4 * T_BYTES)                // Ah,Al,Bh,Bl = 40960
#define G2_SMEM  (3 * G2_STAGE)               // 122880 (3-stage)

// ---------------------------------------------------------------------------
// GEMM1: G = swiglu(X @ w1^T, X @ w3^T), bf16 3-term split
// ---------------------------------------------------------------------------
__global__ void __launch_bounds__(512, 1) gemm1_mma() {
    int e   = blockIdx.z;
    int cnt = g_counts[e];
    int m0  = blockIdx.y * 128;
    if (m0 >= cnt) return;
    int base = g_offs[e];
    int n0   = blockIdx.x * 128;

    extern __shared__ char smem[];
    uint32_t sb = smem_u32(smem);
    int tid = threadIdx.x, lane = tid & 31, wid = tid >> 5;
    int wm = wid & 3, wn = wid >> 2;
    int rl = cnt - m0; if (rl > 128) rl = 128;

    const __nv_bfloat16* Ah  = g_Xh  + (size_t)(base + m0) * DIM;
    const __nv_bfloat16* Al  = g_Xl  + (size_t)(base + m0) * DIM;
    const __nv_bfloat16* B1h = g_w1h + ((size_t)e * HID + n0) * DIM;
    const __nv_bfloat16* B1l = g_w1l + ((size_t)e * HID + n0) * DIM;
    const __nv_bfloat16* B3h = g_w3h + ((size_t)e * HID + n0) * DIM;
    const __nv_bfloat16* B3l = g_w3l + ((size_t)e * HID + n0) * DIM;

    int lr = tid >> 2, lc = tid & 3;           // 128 rows x 4 16B-chunks
    auto load_stage = [&](int ci, int buf) {
        uint32_t s = sb + buf * G1_STAGE;
        int k0 = ci * 32;
        size_t go = (size_t)lr * DIM + k0 + lc * 8;
        uint32_t so = (uint32_t)(lr * ROWB + lc * 16);
        int sz = (lr < rl) ? 16 : 0;
        CP_ASYNC16(s + so,               Ah + go, sz);
        CP_ASYNC16(s + T_BYTES + so,     Al + go, sz);
        uint32_t bb = s + 2 * T_BYTES;
        CP_ASYNC16(bb + so,              B1h + go, 16);
        CP_ASYNC16(bb + T_BYTES + so,    B1l + go, 16);
        CP_ASYNC16(bb + 2 * T_BYTES + so, B3h + go, 16);
        CP_ASYNC16(bb + 3 * T_BYTES + so, B3l + go, 16);
        CP_COMMIT();
    };

    float acc[2][2][4][4];
#pragma unroll
    for (int a = 0; a < 2; a++)
#pragma unroll
        for (int b = 0; b < 2; b++)
#pragma unroll
            for (int c = 0; c < 4; c++)
#pragma unroll
                for (int d = 0; d < 4; d++) acc[a][b][c][d] = 0.0f;

    uint32_t aRow  = (uint32_t)(lane & 15);
    uint32_t aHalf = (uint32_t)((lane >> 4) * 16);
    int g = lane >> 3;
    uint32_t bRowOff = (uint32_t)((((g >> 1) * 8) + (lane & 7)) * ROWB);
    uint32_t bKOff   = (uint32_t)((g & 1) * 16);

    load_stage(0, 0);
    load_stage(1, 1);
    for (int ci = 0; ci < 32; ci++) {
        if (ci == 31) { CP_WAIT0(); } else { CP_WAIT1(); }
        __syncthreads();
        if (ci + 2 < 32) load_stage(ci + 2, (ci + 2) % 3);
        uint32_t s = sb + (ci % 3) * G1_STAGE;
#pragma unroll
        for (int ks = 0; ks < 2; ks++) {
            uint32_t kb = (uint32_t)(ks * 32);
            uint32_t aH[2][4], aL[2][4];
#pragma unroll
            for (int mf = 0; mf < 2; mf++) {
                uint32_t ad = s + (uint32_t)((wm * 32 + mf * 16 + aRow) * ROWB) + kb + aHalf;
                ldsm4(aH[mf], ad);
                ldsm4(aL[mf], ad + T_BYTES);
            }
            uint32_t bb = s + 2 * T_BYTES;
#pragma unroll
            for (int nh = 0; nh < 2; nh++) {
                uint32_t bd = bb + (uint32_t)((wn * 32 + nh * 16) * ROWB) + bRowOff + kb + bKOff;
                uint32_t b1h[4], b1l[4], b3h[4], b3l[4];
                ldsm4(b1h, bd);
                ldsm4(b1l, bd + T_BYTES);
                ldsm4(b3h, bd + 2 * T_BYTES);
                ldsm4(b3l, bd + 3 * T_BYTES);
#pragma unroll
                for (int mf = 0; mf < 2; mf++)
#pragma unroll
                    for (int j = 0; j < 2; j++) {
                        int nf = nh * 2 + j;
                        mma16816(acc[0][mf][nf], aH[mf], &b1h[j * 2]);
                        mma16816(acc[0][mf][nf], aH[mf], &b1l[j * 2]);
                        mma16816(acc[0][mf][nf], aL[mf], &b1h[j * 2]);
                        mma16816(acc[1][mf][nf], aH[mf], &b3h[j * 2]);
                        mma16816(acc[1][mf][nf], aH[mf], &b3l[j * 2]);
                        mma16816(acc[1][mf][nf], aL[mf], &b3h[j * 2]);
                    }
            }
        }
    }

    // Epilogue: swiglu, split, store bf16 hi/lo
#pragma unroll
    for (int mf = 0; mf < 2; mf++) {
#pragma unroll
        for (int nf = 0; nf < 4; nf++) {
            int r   = wm * 32 + mf * 16 + (lane >> 2);
            int col = n0 + wn * 32 + nf * 8 + (lane & 3) * 2;
#pragma unroll
            for (int half = 0; half < 2; half++) {
                int row = r + half * 8;
                if (row < rl) {
                    float h0 = acc[0][mf][nf][half * 2];
                    float h1 = acc[0][mf][nf][half * 2 + 1];
                    float x0 = acc[1][mf][nf][half * 2];
                    float x1 = acc[1][mf][nf][half * 2 + 1];
                    float v0 = h0 * (1.0f / (1.0f + __expf(-h0))) * x0;
                    float v1 = h1 * (1.0f / (1.0f + __expf(-h1))) * x1;
                    __nv_bfloat16 vh0, vl0, vh1, vl1;
                    split_bf16(v0, vh0, vl0);
                    split_bf16(v1, vh1, vl1);
                    size_t o = (size_t)(base + m0 + row) * HID + col;
                    *(__nv_bfloat162*)&g_Gh[o] = __halves2bfloat162(vh0, vh1);
                    *(__nv_bfloat162*)&g_Gl[o] = __halves2bfloat162(vl0, vl1);
                }
            }
        }
    }
}

// ---------------------------------------------------------------------------
// GEMM2: Y[p] = gate[p] * (G[p] @ w2^T), bf16 3-term split
// ---------------------------------------------------------------------------
__global__ void __launch_bounds__(512, 1) gemm2_mma() {
    int e   = blockIdx.z;
    int cnt = g_counts[e];
    int m0  = blockIdx.y * 128;
    if (m0 >= cnt) return;
    int base = g_offs[e];
    int n0   = blockIdx.x * 128;

    extern __shared__ char smem[];
    uint32_t sb = smem_u32(smem);
    int tid = threadIdx.x, lane = tid & 31, wid = tid >> 5;
    int wm = wid & 3, wn = wid >> 2;
    int rl = cnt - m0; if (rl > 128) rl = 128;

    const __nv_bfloat16* Ah = g_Gh  + (size_t)(base + m0) * HID;
    const __nv_bfloat16* Al = g_Gl  + (size_t)(base + m0) * HID;
    const __nv_bfloat16* Bh = g_w2h + ((size_t)e * DIM + n0) * HID;
    const __nv_bfloat16* Bl = g_w2l + ((size_t)e * DIM + n0) * HID;

    int lr = tid >> 2, lc = tid & 3;
    auto load_stage = [&](int ci, int buf) {
        uint32_t s = sb + buf * G2_STAGE;
        int k0 = ci * 32;
        size_t go = (size_t)lr * HID + k0 + lc * 8;
        uint32_t so = (uint32_t)(lr * ROWB + lc * 16);
        int sz = (lr < rl) ? 16 : 0;
        CP_ASYNC16(s + so,            Ah + go, sz);
        CP_ASYNC16(s + T_BYTES + so,  Al + go, sz);
        uint32_t bb = s + 2 * T_BYTES;
        CP_ASYNC16(bb + so,           Bh + go, 16);
        CP_ASYNC16(bb + T_BYTES + so, Bl + go, 16);
        CP_COMMIT();
    };

    float acc[2][4][4];
#pragma unroll
    for (int a = 0; a < 2; a++)
#pragma unroll
        for (int c = 0; c < 4; c++)
#pragma unroll
            for (int d = 0; d < 4; d++) acc[a][c][d] = 0.0f;

    uint32_t aRow  = (uint32_t)(lane & 15);
    uint32_t aHalf = (uint32_t)((lane >> 4) * 16);
    int g = lane >> 3;
    uint32_t bRowOff = (uint32_t)((((g >> 1) * 8) + (lane & 7)) * ROWB);
    uint32_t bKOff   = (uint32_t)((g & 1) * 16);

    load_stage(0, 0);
    load_stage(1, 1);
    for (int ci = 0; ci < 64; ci++) {
        if (ci == 63) { CP_WAIT0(); } else { CP_WAIT1(); }
        __syncthreads();
        if (ci + 2 < 64) load_stage(ci + 2, (ci + 2) % 3);
        uint32_t s = sb + (ci % 3) * G2_STAGE;
#pragma unroll
        for (int ks = 0; ks < 2; ks++) {
            uint32_t kb = (uint32_t)(ks * 32);
            uint32_t aH[2][4], aL[2][4];
#pragma unroll
            for (int mf = 0; mf < 2; mf++) {
                uint32_t ad = s + (uint32_t)((wm * 32 + mf * 16 + aRow) * ROWB) + kb + aHalf;
                ldsm4(aH[mf], ad);
                ldsm4(aL[mf], ad + T_BYTES);
            }
            uint32_t bb = s + 2 * T_BYTES;
#pragma unroll
            for (int nh = 0; nh < 2; nh++) {
                uint32_t bd = bb + (uint32_t)((wn * 32 + nh * 16) * ROWB) + bRowOff + kb + bKOff;
                uint32_t bh[4], bl[4];
                ldsm4(bh, bd);
                ldsm4(bl, bd + T_BYTES);
#pragma unroll
                for (int mf = 0; mf < 2; mf++)
#pragma unroll
                    for (int j = 0; j < 2; j++) {
                        int nf = nh * 2 + j;
                        mma16816(acc[mf][nf], aH[mf], &bh[j * 2]);
                        mma16816(acc[mf][nf], aH[mf], &bl[j * 2]);
                        mma16816(acc[mf][nf], aL[mf], &bh[j * 2]);
                    }
            }
        }
    }

    // Epilogue: gate-scale, store fp32 rows of Y
#pragma unroll
    for (int mf = 0; mf < 2; mf++) {
#pragma unroll
        for (int nf = 0; nf < 4; nf++) {
            int r   = wm * 32 + mf * 16 + (lane >> 2);
            int col = n0 + wn * 32 + nf * 8 + (lane & 3) * 2;
#pragma unroll
            for (int half = 0; half < 2; half++) {
                int row = r + half * 8;
                if (row < rl) {
                    float gate = g_cgate[base + m0 + row];
                    float2 v;
                    v.x = gate * acc[mf][nf][half * 2];
                    v.y = gate * acc[mf][nf][half * 2 + 1];
                    *(float2*)&g_Y[(size_t)(base + m0 + row) * DIM + col] = v;
                }
            }
        }
    }
}

// ---------------------------------------------------------------------------
// Combine: out[token] = Y[pair0] + Y[pair1]
// ---------------------------------------------------------------------------
__global__ void combine_kernel(float* __restrict__ out) {
    int t = blockIdx.x;
    int e0 = g_tslot[2 * t], e1 = g_tslot[2 * t + 1];
    int p0 = g_offs[e0 >> 13] + (e0 & (TOK - 1));
    int p1 = g_offs[e1 >> 13] + (e1 & (TOK - 1));
    float4 a = ((const float4*)(g_Y + (size_t)p0 * DIM))[threadIdx.x];
    float4 b = ((const float4*)(g_Y + (size_t)p1 * DIM))[threadIdx.x];
    float4 r = make_float4(a.x + b.x, a.y + b.y, a.z + b.z, a.w + b.w);
    ((float4*)(out + (size_t)t * DIM))[threadIdx.x] = r;
}

// ---------------------------------------------------------------------------
// Launch
// ---------------------------------------------------------------------------
extern "C" void kernel_launch(void* const* d_in, const int* in_sizes, int n_in,
                              void* d_out, int out_size)
{
    const float* x     = (const float*)d_in[0];
    const float* noise = (const float*)d_in[1];
    const float* rw    = (const float*)d_in[2];
    const float* rb    = (const float*)d_in[3];
    const float* nw    = (const float*)d_in[4];
    const float* nb    = (const float*)d_in[5];
    const float* w1    = (const float*)d_in[6];
    const float* w2    = (const float*)d_in[7];
    const float* w3    = (const float*)d_in[8];
    float* out = (float*)d_out;

    cudaFuncSetAttribute(gemm1_mma, cudaFuncAttributeMaxDynamicSharedMemorySize, G1_SMEM);
    cudaFuncSetAttribute(gemm2_mma, cudaFuncAttributeMaxDynamicSharedMemorySize, G2_SMEM);

    const int n4 = (NE * HID * DIM) / 4;

    zero_counts_kernel<<<1, 32>>>();
    convert_kernel<<<3 * (n4 / 256), 256>>>(w1, w2, w3, n4);
    router_kernel<<<TOK / 8, 256>>>(x, noise, rw, rb, nw, nb);
    scan_offsets_kernel<<<1, 32>>>();
    gather_kernel<<<NE * TOK, 256>>>(x);
    gemm1_mma<<<dim3(HID / 128, TOK / 128, NE), 512, G1_SMEM>>>();
    gemm2_mma<<<dim3(DIM / 128, TOK / 128, NE), 512, G2_SMEM>>>();
    combine_kernel<<<TOK, 256>>>(out);
}

// round 14
// speedup vs baseline: 1.0197x; 1.0197x over previous
#include <cuda_runtime.h>
#include <cuda_bf16.h>
#include <stdint.h>
#include <math.h>

// Problem constants
#define TOK   8192
#define DIM   1024
#define HID   2048
#define NE    8
#define NPAIR (TOK * 2)

// ---------------------------------------------------------------------------
// Device scratch
// ---------------------------------------------------------------------------
__device__ int   g_counts[NE];
__device__ int   g_offs[NE];
__device__ int   g_done;
__device__ int   g_ptoken[NE * TOK];
__device__ float g_pgate [NE * TOK];
__device__ float g_cgate [NPAIR];
__device__ int   g_tslot [NPAIR];

__device__ __nv_bfloat16 g_w1h[(size_t)NE * HID * DIM];
__device__ __nv_bfloat16 g_w1l[(size_t)NE * HID * DIM];
__device__ __nv_bfloat16 g_w3h[(size_t)NE * HID * DIM];
__device__ __nv_bfloat16 g_w3l[(size_t)NE * HID * DIM];
__device__ __nv_bfloat16 g_w2h[(size_t)NE * DIM * HID];
__device__ __nv_bfloat16 g_w2l[(size_t)NE * DIM * HID];

__device__ __nv_bfloat16 g_Xh[(size_t)NPAIR * DIM];
__device__ __nv_bfloat16 g_Xl[(size_t)NPAIR * DIM];
__device__ __nv_bfloat16 g_Gh[(size_t)NPAIR * HID];
__device__ __nv_bfloat16 g_Gl[(size_t)NPAIR * HID];
__device__ float         g_Y [(size_t)NPAIR * DIM];

// ---------------------------------------------------------------------------
// Helpers
// ---------------------------------------------------------------------------
__device__ __forceinline__ uint32_t smem_u32(const void* p) {
    uint32_t a;
    asm("{ .reg .u64 t; cvta.to.shared.u64 t, %1; cvt.u32.u64 %0, t; }"
        : "=r"(a) : "l"(p));
    return a;
}

#define CP_ASYNC16(dst, src, sz) \
    asm volatile("cp.async.cg.shared.global [%0], [%1], 16, %2;" \
                 :: "r"(dst), "l"(src), "r"(sz))
#define CP_COMMIT() asm volatile("cp.async.commit_group;")
#define CP_WAIT1()  asm volatile("cp.async.wait_group 1;")
#define CP_WAIT0()  asm volatile("cp.async.wait_group 0;")

__device__ __forceinline__ void ldsm4(uint32_t* r, uint32_t addr) {
    asm volatile("ldmatrix.sync.aligned.m8n8.x4.shared.b16 {%0,%1,%2,%3}, [%4];"
                 : "=r"(r[0]), "=r"(r[1]), "=r"(r[2]), "=r"(r[3]) : "r"(addr));
}

__device__ __forceinline__ void mma16816(float* c, const uint32_t* a, const uint32_t* b) {
    asm volatile(
        "mma.sync.aligned.m16n8k16.row.col.f32.bf16.bf16.f32 "
        "{%0,%1,%2,%3}, {%4,%5,%6,%7}, {%8,%9}, {%0,%1,%2,%3};"
        : "+f"(c[0]), "+f"(c[1]), "+f"(c[2]), "+f"(c[3])
        : "r"(a[0]), "r"(a[1]), "r"(a[2]), "r"(a[3]), "r"(b[0]), "r"(b[1]));
}

__device__ __forceinline__ void split_bf16(float v, __nv_bfloat16& h, __nv_bfloat16& l) {
    h = __float2bfloat16(v);
    l = __float2bfloat16(v - __bfloat162float(h));
}

// ---------------------------------------------------------------------------
// Launch 1: weight conversion fp32 -> bf16 hi/lo; block 0 zeroes counters
// ---------------------------------------------------------------------------
__global__ void convert_kernel(const float* __restrict__ w1,
                               const float* __restrict__ w2,
                               const float* __restrict__ w3, int n4) {
    if (blockIdx.x == 0) {
        if (threadIdx.x < NE) g_counts[threadIdx.x] = 0;
        if (threadIdx.x == NE) g_done = 0;
    }
    int blk_per = n4 / 256;
    int which = blockIdx.x / blk_per;
    int i = (blockIdx.x - which * blk_per) * 256 + threadIdx.x;
    const float* s;
    __nv_bfloat16 *h, *l;
    if (which == 0)      { s = w1; h = g_w1h; l = g_w1l; }
    else if (which == 1) { s = w3; h = g_w3h; l = g_w3l; }
    else                 { s = w2; h = g_w2h; l = g_w2l; }
    float4 v = ((const float4*)s)[i];
    __nv_bfloat16 hx, lx, hy, ly, hz, lz, hw, lw;
    split_bf16(v.x, hx, lx); split_bf16(v.y, hy, ly);
    split_bf16(v.z, hz, lz); split_bf16(v.w, hw, lw);
    ((__nv_bfloat162*)h)[2 * i]     = __halves2bfloat162(hx, hy);
    ((__nv_bfloat162*)h)[2 * i + 1] = __halves2bfloat162(hz, hw);
    ((__nv_bfloat162*)l)[2 * i]     = __halves2bfloat162(lx, ly);
    ((__nv_bfloat162*)l)[2 * i + 1] = __halves2bfloat162(lz, lw);
}

// ---------------------------------------------------------------------------
// Launch 2: router (noisy top-2) + last-block prefix scan into g_offs
// ---------------------------------------------------------------------------
__global__ void router_kernel(const float* __restrict__ x,
                              const float* __restrict__ noise,
                              const float* __restrict__ rw,
                              const float* __restrict__ rb,
                              const float* __restrict__ nw,
                              const float* __restrict__ nb)
{
    int gwarp = (int)((blockIdx.x * blockDim.x + threadIdx.x) >> 5);
    int lane  = threadIdx.x & 31;
    // grid is sized so gwarp < TOK always (1024 blocks * 8 warps = 8192)
    const float* xr = x + (size_t)gwarp * DIM;

    float accR[NE], accN[NE];
#pragma unroll
    for (int e = 0; e < NE; e++) { accR[e] = 0.0f; accN[e] = 0.0f; }
    for (int i = lane; i < DIM; i += 32) {
        float xv = xr[i];
#pragma unroll
        for (int e = 0; e < NE; e++) {
            accR[e] = fmaf(xv, rw[e * DIM + i], accR[e]);
            accN[e] = fmaf(xv, nw[e * DIM + i], accN[e]);
        }
    }
#pragma unroll
    for (int e = 0; e < NE; e++) {
#pragma unroll
        for (int o = 16; o > 0; o >>= 1) {
            accR[e] += __shfl_xor_sync(0xffffffffu, accR[e], o);
            accN[e] += __shfl_xor_sync(0xffffffffu, accN[e], o);
        }
    }
    if (lane == 0) {
        float noisy[NE];
#pragma unroll
        for (int e = 0; e < NE; e++) {
            float lg = accR[e] + rb[e];
            float nl = accN[e] + nb[e];
            float sp = fmaxf(nl, 0.0f) + log1pf(expf(-fabsf(nl)));
            noisy[e] = lg + noise[(size_t)gwarp * NE + e] * sp;
        }
        int i1 = 0;
#pragma unroll
        for (int e = 1; e < NE; e++) if (noisy[e] > noisy[i1]) i1 = e;
        int i2 = (i1 == 0) ? 1 : 0;
#pragma unroll
        for (int e = 0; e < NE; e++) {
            if (e == i1 || e == i2) continue;
            if (noisy[e] > noisy[i2]) i2 = e;
        }
        float e2 = expf(noisy[i2] - noisy[i1]);
        float inv = 1.0f / (1.0f + e2);
        int s1 = atomicAdd(&g_counts[i1], 1);
        g_ptoken[i1 * TOK + s1] = gwarp;
        g_pgate [i1 * TOK + s1] = inv;
        int s2 = atomicAdd(&g_counts[i2], 1);
        g_ptoken[i2 * TOK + s2] = gwarp;
        g_pgate [i2 * TOK + s2] = e2 * inv;
        g_tslot[2 * gwarp]     = i1 * TOK + s1;
        g_tslot[2 * gwarp + 1] = i2 * TOK + s2;
    }

    // last-arriving block computes the 8-entry prefix scan into g_offs
    __syncthreads();
    __threadfence();
    if (threadIdx.x == 0) {
        int t = atomicAdd(&g_done, 1);
        if (t == (int)gridDim.x - 1) {
            int s = 0;
#pragma unroll
            for (int e = 0; e < NE; e++) { g_offs[e] = s; s += g_counts[e]; }
        }
    }
}

// ---------------------------------------------------------------------------
// Launch 3: gather + bf16 hi/lo split (R7-proven indexing via g_offs)
// ---------------------------------------------------------------------------
__global__ void gather_kernel(const float* __restrict__ x) {
    int e    = blockIdx.x >> 13;
    int slot = blockIdx.x & (TOK - 1);
    if (slot >= g_counts[e]) return;
    int token = g_ptoken[e * TOK + slot];
    int p     = g_offs[e] + slot;

    float4 v = ((const float4*)(x + (size_t)token * DIM))[threadIdx.x];
    __nv_bfloat16 hx, lx, hy, ly, hz, lz, hw, lw;
    split_bf16(v.x, hx, lx); split_bf16(v.y, hy, ly);
    split_bf16(v.z, hz, lz); split_bf16(v.w, hw, lw);
    size_t o = (size_t)p * DIM + (size_t)threadIdx.x * 4;
    *(__nv_bfloat162*)&g_Xh[o]     = __halves2bfloat162(hx, hy);
    *(__nv_bfloat162*)&g_Xh[o + 2] = __halves2bfloat162(hz, hw);
    *(__nv_bfloat162*)&g_Xl[o]     = __halves2bfloat162(lx, ly);
    *(__nv_bfloat162*)&g_Xl[o + 2] = __halves2bfloat162(lz, lw);

    if (threadIdx.x == 0) g_cgate[p] = g_pgate[e * TOK + slot];
}

// ---------------------------------------------------------------------------
// GEMM tiling constants (R7 proven config)
// ---------------------------------------------------------------------------
#define ROWB     80
#define A_BYTES  (128 * ROWB)   // 10240
#define B_BYTES  (64 * ROWB)    // 5120

#define G1_STAGE (2 * A_BYTES + 4 * B_BYTES)  // 40960
#define G1_SMEM  (2 * G1_STAGE)               // 81920
#define G2_STAGE (2 * A_BYTES + 2 * B_BYTES)  // 30720
#define G2_SMEM  (2 * G2_STAGE)               // 61440

// ---------------------------------------------------------------------------
// Launch 4: GEMM1 — G = swiglu(X @ w1^T, X @ w3^T), bf16 3-term split
// block 128x64(per matrix), BK=32, 8 warps (4x2), warp 32x32, occupancy 2
// ---------------------------------------------------------------------------
__global__ void __launch_bounds__(256, 2) gemm1_mma() {
    int e   = blockIdx.z;
    int cnt = g_counts[e];
    int m0  = blockIdx.y * 128;
    if (m0 >= cnt) return;
    int base = g_offs[e];
    int n0   = blockIdx.x * 64;

    extern __shared__ char smem[];
    uint32_t sb = smem_u32(smem);
    int tid = threadIdx.x, lane = tid & 31, wid = tid >> 5;
    int wm = wid >> 1, wn = wid & 1;
    int rl = cnt - m0; if (rl > 128) rl = 128;

    const __nv_bfloat16* Ah  = g_Xh  + (size_t)(base + m0) * DIM;
    const __nv_bfloat16* Al  = g_Xl  + (size_t)(base + m0) * DIM;
    const __nv_bfloat16* B1h = g_w1h + ((size_t)e * HID + n0) * DIM;
    const __nv_bfloat16* B1l = g_w1l + ((size_t)e * HID + n0) * DIM;
    const __nv_bfloat16* B3h = g_w3h + ((size_t)e * HID + n0) * DIM;
    const __nv_bfloat16* B3l = g_w3l + ((size_t)e * HID + n0) * DIM;

    auto load_stage = [&](int ci, int buf) {
        uint32_t s = sb + buf * G1_STAGE;
        int k0 = ci * 32;
#pragma unroll
        for (int it = 0; it < 2; it++) {
            int id = it * 256 + tid;
            int r = id >> 2, c = id & 3;
            int sz = (r < rl) ? 16 : 0;
            size_t go = (size_t)r * DIM + k0 + c * 8;
            uint32_t so = (uint32_t)(r * ROWB + c * 16);
            CP_ASYNC16(s + so,           Ah + go, sz);
            CP_ASYNC16(s + A_BYTES + so, Al + go, sz);
        }
        {
            int r = tid >> 2, c = tid & 3;
            size_t go = (size_t)r * DIM + k0 + c * 8;
            uint32_t so = (uint32_t)(r * ROWB + c * 16);
            uint32_t bb = s + 2 * A_BYTES;
            CP_ASYNC16(bb + so,               B1h + go, 16);
            CP_ASYNC16(bb + B_BYTES + so,     B1l + go, 16);
            CP_ASYNC16(bb + 2 * B_BYTES + so, B3h + go, 16);
            CP_ASYNC16(bb + 3 * B_BYTES + so, B3l + go, 16);
        }
        CP_COMMIT();
    };

    float acc[2][2][4][4];
#pragma unroll
    for (int a = 0; a < 2; a++)
#pragma unroll
        for (int b = 0; b < 2; b++)
#pragma unroll
            for (int c = 0; c < 4; c++)
#pragma unroll
                for (int d = 0; d < 4; d++) acc[a][b][c][d] = 0.0f;

    uint32_t aRow  = (uint32_t)(lane & 15);
    uint32_t aHalf = (uint32_t)((lane >> 4) * 16);
    int g = lane >> 3;
    uint32_t bRowOff = (uint32_t)((((g >> 1) * 8) + (lane & 7)) * ROWB);
    uint32_t bKOff   = (uint32_t)((g & 1) * 16);

    load_stage(0, 0);
    for (int ci = 0; ci < 32; ci++) {
        int b = ci & 1;
        if (ci + 1 < 32) { load_stage(ci + 1, b ^ 1); CP_WAIT1(); }
        else             { CP_WAIT0(); }
        __syncthreads();
        uint32_t s = sb + b * G1_STAGE;
#pragma unroll
        for (int ks = 0; ks < 2; ks++) {
            uint32_t kb = (uint32_t)(ks * 32);
            uint32_t aH[2][4], aL[2][4];
#pragma unroll
            for (int mf = 0; mf < 2; mf++) {
                uint32_t ad = s + (uint32_t)((wm * 32 + mf * 16 + aRow) * ROWB) + kb + aHalf;
                ldsm4(aH[mf], ad);
                ldsm4(aL[mf], ad + A_BYTES);
            }
            uint32_t bb = s + 2 * A_BYTES;
#pragma unroll
            for (int nh = 0; nh < 2; nh++) {
                uint32_t bd = bb + (uint32_t)((wn * 32 + nh * 16) * ROWB) + bRowOff + kb + bKOff;
                uint32_t b1h[4], b1l[4], b3h[4], b3l[4];
                ldsm4(b1h, bd);
                ldsm4(b1l, bd + B_BYTES);
                ldsm4(b3h, bd + 2 * B_BYTES);
                ldsm4(b3l, bd + 3 * B_BYTES);
#pragma unroll
                for (int mf = 0; mf < 2; mf++)
#pragma unroll
                    for (int j = 0; j < 2; j++) {
                        int nf = nh * 2 + j;
                        mma16816(acc[0][mf][nf], aH[mf], &b1h[j * 2]);
                        mma16816(acc[0][mf][nf], aH[mf], &b1l[j * 2]);
                        mma16816(acc[0][mf][nf], aL[mf], &b1h[j * 2]);
                        mma16816(acc[1][mf][nf], aH[mf], &b3h[j * 2]);
                        mma16816(acc[1][mf][nf], aH[mf], &b3l[j * 2]);
                        mma16816(acc[1][mf][nf], aL[mf], &b3h[j * 2]);
                    }
            }
        }
        __syncthreads();
    }

    // Epilogue: swiglu, split, store bf16 hi/lo
#pragma unroll
    for (int mf = 0; mf < 2; mf++) {
#pragma unroll
        for (int nf = 0; nf < 4; nf++) {
            int r   = wm * 32 + mf * 16 + (lane >> 2);
            int col = n0 + wn * 32 + nf * 8 + (lane & 3) * 2;
#pragma unroll
            for (int half = 0; half < 2; half++) {
                int row = r + half * 8;
                if (row < rl) {
                    float h0 = acc[0][mf][nf][half * 2];
                    float h1 = acc[0][mf][nf][half * 2 + 1];
                    float x0 = acc[1][mf][nf][half * 2];
                    float x1 = acc[1][mf][nf][half * 2 + 1];
                    float v0 = h0 * (1.0f / (1.0f + __expf(-h0))) * x0;
                    float v1 = h1 * (1.0f / (1.0f + __expf(-h1))) * x1;
                    __nv_bfloat16 vh0, vl0, vh1, vl1;
                    split_bf16(v0, vh0, vl0);
                    split_bf16(v1, vh1, vl1);
                    size_t o = (size_t)(base + m0 + row) * HID + col;
                    *(__nv_bfloat162*)&g_Gh[o] = __halves2bfloat162(vh0, vh1);
                    *(__nv_bfloat162*)&g_Gl[o] = __halves2bfloat162(vl0, vl1);
                }
            }
        }
    }
}

// ---------------------------------------------------------------------------
// Launch 5: GEMM2 — Y[p] = gate[p] * (G[p] @ w2^T), bf16 3-term split
// ---------------------------------------------------------------------------
__global__ void __launch_bounds__(256, 2) gemm2_mma() {
    int e   = blockIdx.z;
    int cnt = g_counts[e];
    int m0  = blockIdx.y * 128;
    if (m0 >= cnt) return;
    int base = g_offs[e];
    int n0   = blockIdx.x * 64;

    extern __shared__ char smem[];
    uint32_t sb = smem_u32(smem);
    int tid = threadIdx.x, lane = tid & 31, wid = tid >> 5;
    int wm = wid >> 1, wn = wid & 1;
    int rl = cnt - m0; if (rl > 128) rl = 128;

    const __nv_bfloat16* Ah = g_Gh  + (size_t)(base + m0) * HID;
    const __nv_bfloat16* Al = g_Gl  + (size_t)(base + m0) * HID;
    const __nv_bfloat16* Bh = g_w2h + ((size_t)e * DIM + n0) * HID;
    const __nv_bfloat16* Bl = g_w2l + ((size_t)e * DIM + n0) * HID;

    auto load_stage = [&](int ci, int buf) {
        uint32_t s = sb + buf * G2_STAGE;
        int k0 = ci * 32;
#pragma unroll
        for (int it = 0; it < 2; it++) {
            int id = it * 256 + tid;
            int r = id >> 2, c = id & 3;
            int sz = (r < rl) ? 16 : 0;
            size_t go = (size_t)r * HID + k0 + c * 8;
            uint32_t so = (uint32_t)(r * ROWB + c * 16);
            CP_ASYNC16(s + so,           Ah + go, sz);
            CP_ASYNC16(s + A_BYTES + so, Al + go, sz);
        }
        {
            int r = tid >> 2, c = tid & 3;
            size_t go = (size_t)r * HID + k0 + c * 8;
            uint32_t so = (uint32_t)(r * ROWB + c * 16);
            uint32_t bb = s + 2 * A_BYTES;
            CP_ASYNC16(bb + so,           Bh + go, 16);
            CP_ASYNC16(bb + B_BYTES + so, Bl + go, 16);
        }
        CP_COMMIT();
    };

    float acc[2][4][4];
#pragma unroll
    for (int a = 0; a < 2; a++)
#pragma unroll
        for (int c = 0; c < 4; c++)
#pragma unroll
            for (int d = 0; d < 4; d++) acc[a][c][d] = 0.0f;

    uint32_t aRow  = (uint32_t)(lane & 15);
    uint32_t aHalf = (uint32_t)((lane >> 4) * 16);
    int g = lane >> 3;
    uint32_t bRowOff = (uint32_t)((((g >> 1) * 8) + (lane & 7)) * ROWB);
    uint32_t bKOff   = (uint32_t)((g & 1) * 16);

    load_stage(0, 0);
    for (int ci = 0; ci < 64; ci++) {
        int b = ci & 1;
        if (ci + 1 < 64) { load_stage(ci + 1, b ^ 1); CP_WAIT1(); }
        else             { CP_WAIT0(); }
        __syncthreads();
        uint32_t s = sb + b * G2_STAGE;
#pragma unroll
        for (int ks = 0; ks < 2; ks++) {
            uint32_t kb = (uint32_t)(ks * 32);
            uint32_t aH[2][4], aL[2][4];
#pragma unroll
            for (int mf = 0; mf < 2; mf++) {
                uint32_t ad = s + (uint32_t)((wm * 32 + mf * 16 + aRow) * ROWB) + kb + aHalf;
                ldsm4(aH[mf], ad);
                ldsm4(aL[mf], ad + A_BYTES);
            }
            uint32_t bb = s + 2 * A_BYTES;
#pragma unroll
            for (int nh = 0; nh < 2; nh++) {
                uint32_t bd = bb + (uint32_t)((wn * 32 + nh * 16) * ROWB) + bRowOff + kb + bKOff;
                uint32_t bh[4], bl[4];
                ldsm4(bh, bd);
                ldsm4(bl, bd + B_BYTES);
#pragma unroll
                for (int mf = 0; mf < 2; mf++)
#pragma unroll
                    for (int j = 0; j < 2; j++) {
                        int nf = nh * 2 + j;
                        mma16816(acc[mf][nf], aH[mf], &bh[j * 2]);
                        mma16816(acc[mf][nf], aH[mf], &bl[j * 2]);
                        mma16816(acc[mf][nf], aL[mf], &bh[j * 2]);
                    }
            }
        }
        __syncthreads();
    }

    // Epilogue: gate-scale, store fp32 rows of Y
#pragma unroll
    for (int mf = 0; mf < 2; mf++) {
#pragma unroll
        for (int nf = 0; nf < 4; nf++) {
            int r   = wm * 32 + mf * 16 + (lane >> 2);
            int col = n0 + wn * 32 + nf * 8 + (lane & 3) * 2;
#pragma unroll
            for (int half = 0; half < 2; half++) {
                int row = r + half * 8;
                if (row < rl) {
                    float gate = g_cgate[base + m0 + row];
                    float2 v;
                    v.x = gate * acc[mf][nf][half * 2];
                    v.y = gate * acc[mf][nf][half * 2 + 1];
                    *(float2*)&g_Y[(size_t)(base + m0 + row) * DIM + col] = v;
                }
            }
        }
    }
}

// ---------------------------------------------------------------------------
// Launch 6: combine — out[token] = Y[pair0] + Y[pair1]
// ---------------------------------------------------------------------------
__global__ void combine_kernel(float* __restrict__ out) {
    int t = blockIdx.x;
    int e0 = g_tslot[2 * t], e1 = g_tslot[2 * t + 1];
    int p0 = g_offs[e0 >> 13] + (e0 & (TOK - 1));
    int p1 = g_offs[e1 >> 13] + (e1 & (TOK - 1));
    float4 a = ((const float4*)(g_Y + (size_t)p0 * DIM))[threadIdx.x];
    float4 b = ((const float4*)(g_Y + (size_t)p1 * DIM))[threadIdx.x];
    float4 r = make_float4(a.x + b.x, a.y + b.y, a.z + b.z, a.w + b.w);
    ((float4*)(out + (size_t)t * DIM))[threadIdx.x] = r;
}

// ---------------------------------------------------------------------------
// Launch
// ---------------------------------------------------------------------------
extern "C" void kernel_launch(void* const* d_in, const int* in_sizes, int n_in,
                              void* d_out, int out_size)
{
    const float* x     = (const float*)d_in[0];
    const float* noise = (const float*)d_in[1];
    const float* rw    = (const float*)d_in[2];
    const float* rb    = (const float*)d_in[3];
    const float* nw    = (const float*)d_in[4];
    const float* nb    = (const float*)d_in[5];
    const float* w1    = (const float*)d_in[6];
    const float* w2    = (const float*)d_in[7];
    const float* w3    = (const float*)d_in[8];
    float* out = (float*)d_out;

    cudaFuncSetAttribute(gemm1_mma, cudaFuncAttributeMaxDynamicSharedMemorySize, G1_SMEM);
    cudaFuncSetAttribute(gemm2_mma, cudaFuncAttributeMaxDynamicSharedMemorySize, G2_SMEM);

    const int n4 = (NE * HID * DIM) / 4;

    convert_kernel<<<3 * (n4 / 256), 256>>>(w1, w2, w3, n4);          // 1 (zeros counts+done)
    router_kernel<<<TOK / 8, 256>>>(x, noise, rw, rb, nw, nb);        // 2 (+ tail scan)
    gather_kernel<<<NE * TOK, 256>>>(x);                              // 3
    gemm1_mma<<<dim3(HID / 64, TOK / 128, NE), 256, G1_SMEM>>>();     // 4 <- ncu capture slot
    gemm2_mma<<<dim3(DIM / 64, TOK / 128, NE), 256, G2_SMEM>>>();     // 5
    combine_kernel<<<TOK, 256>>>(out);                                // 6
}

// round 16
// speedup vs baseline: 1.3418x; 1.3159x over previous
#include <cuda_runtime.h>
#include <cuda_bf16.h>
#include <cuda_fp16.h>
#include <stdint.h>
#include <math.h>

// Problem constants
#define TOK   8192
#define DIM   1024
#define HID   2048
#define NE    8
#define NPAIR (TOK * 2)

// ---------------------------------------------------------------------------
// Device scratch
// ---------------------------------------------------------------------------
__device__ int   g_counts[NE];
__device__ int   g_offs[NE];
__device__ int   g_done;
__device__ int   g_ptoken[NE * TOK];
__device__ float g_pgate [NE * TOK];
__device__ float g_cgate [NPAIR];
__device__ int   g_tslot [NPAIR];

__device__ __half g_w1f[(size_t)NE * HID * DIM];
__device__ __half g_w3f[(size_t)NE * HID * DIM];
__device__ __half g_w2f[(size_t)NE * DIM * HID];

__device__ __half g_Xf[(size_t)NPAIR * DIM];
__device__ __half g_Xe[(size_t)NPAIR * DIM];
__device__ __half g_Gf[(size_t)NPAIR * HID];
__device__ __half g_Ge[(size_t)NPAIR * HID];
__device__ float  g_Y [(size_t)NPAIR * DIM];

// ---------------------------------------------------------------------------
// Helpers
// ---------------------------------------------------------------------------
__device__ __forceinline__ uint32_t smem_u32(const void* p) {
    uint32_t a;
    asm("{ .reg .u64 t; cvta.to.shared.u64 t, %1; cvt.u32.u64 %0, t; }"
        : "=r"(a) : "l"(p));
    return a;
}

#define CP_ASYNC16(dst, src, sz) \
    asm volatile("cp.async.cg.shared.global [%0], [%1], 16, %2;" \
                 :: "r"(dst), "l"(src), "r"(sz))
#define CP_COMMIT() asm volatile("cp.async.commit_group;")
#define CP_WAIT1()  asm volatile("cp.async.wait_group 1;")
#define CP_WAIT0()  asm volatile("cp.async.wait_group 0;")

__device__ __forceinline__ void ldsm4(uint32_t* r, uint32_t addr) {
    asm volatile("ldmatrix.sync.aligned.m8n8.x4.shared.b16 {%0,%1,%2,%3}, [%4];"
                 : "=r"(r[0]), "=r"(r[1]), "=r"(r[2]), "=r"(r[3]) : "r"(addr));
}

__device__ __forceinline__ void mma16816(float* c, const uint32_t* a, const uint32_t* b) {
    asm volatile(
        "mma.sync.aligned.m16n8k16.row.col.f32.f16.f16.f32 "
        "{%0,%1,%2,%3}, {%4,%5,%6,%7}, {%8,%9}, {%0,%1,%2,%3};"
        : "+f"(c[0]), "+f"(c[1]), "+f"(c[2]), "+f"(c[3])
        : "r"(a[0]), "r"(a[1]), "r"(a[2]), "r"(a[3]), "r"(b[0]), "r"(b[1]));
}

__device__ __forceinline__ void split_fp16(float v, __half& h, __half& l) {
    h = __float2half_rn(v);
    l = __float2half_rn(v - __half2float(h));
}

// ---------------------------------------------------------------------------
// Launch 1: weight conversion fp32 -> fp16; block 0 zeroes counters
// ---------------------------------------------------------------------------
__global__ void convert_kernel(const float* __restrict__ w1,
                               const float* __restrict__ w2,
                               const float* __restrict__ w3, int n4) {
    if (blockIdx.x == 0) {
        if (threadIdx.x < NE) g_counts[threadIdx.x] = 0;
        if (threadIdx.x == NE) g_done = 0;
    }
    int blk_per = n4 / 256;
    int which = blockIdx.x / blk_per;
    int i = (blockIdx.x - which * blk_per) * 256 + threadIdx.x;
    const float* s;
    __half* h;
    if (which == 0)      { s = w1; h = g_w1f; }
    else if (which == 1) { s = w3; h = g_w3f; }
    else                 { s = w2; h = g_w2f; }
    float4 v = ((const float4*)s)[i];
    __half2 p0 = __halves2half2(__float2half_rn(v.x), __float2half_rn(v.y));
    __half2 p1 = __halves2half2(__float2half_rn(v.z), __float2half_rn(v.w));
    ((__half2*)h)[2 * i]     = p0;
    ((__half2*)h)[2 * i + 1] = p1;
}

// ---------------------------------------------------------------------------
// Launch 2: router (noisy top-2) + last-block prefix scan into g_offs
// ---------------------------------------------------------------------------
__global__ void router_kernel(const float* __restrict__ x,
                              const float* __restrict__ noise,
                              const float* __restrict__ rw,
                              const float* __restrict__ rb,
                              const float* __restrict__ nw,
                              const float* __restrict__ nb)
{
    int gwarp = (int)((blockIdx.x * blockDim.x + threadIdx.x) >> 5);
    int lane  = threadIdx.x & 31;
    const float* xr = x + (size_t)gwarp * DIM;

    float accR[NE], accN[NE];
#pragma unroll
    for (int e = 0; e < NE; e++) { accR[e] = 0.0f; accN[e] = 0.0f; }
    for (int i = lane; i < DIM; i += 32) {
        float xv = xr[i];
#pragma unroll
        for (int e = 0; e < NE; e++) {
            accR[e] = fmaf(xv, rw[e * DIM + i], accR[e]);
            accN[e] = fmaf(xv, nw[e * DIM + i], accN[e]);
        }
    }
#pragma unroll
    for (int e = 0; e < NE; e++) {
#pragma unroll
        for (int o = 16; o > 0; o >>= 1) {
            accR[e] += __shfl_xor_sync(0xffffffffu, accR[e], o);
            accN[e] += __shfl_xor_sync(0xffffffffu, accN[e], o);
        }
    }
    if (lane == 0) {
        float noisy[NE];
#pragma unroll
        for (int e = 0; e < NE; e++) {
            float lg = accR[e] + rb[e];
            float nl = accN[e] + nb[e];
            float sp = fmaxf(nl, 0.0f) + log1pf(expf(-fabsf(nl)));
            noisy[e] = lg + noise[(size_t)gwarp * NE + e] * sp;
        }
        int i1 = 0;
#pragma unroll
        for (int e = 1; e < NE; e++) if (noisy[e] > noisy[i1]) i1 = e;
        int i2 = (i1 == 0) ? 1 : 0;
#pragma unroll
        for (int e = 0; e < NE; e++) {
            if (e == i1 || e == i2) continue;
            if (noisy[e] > noisy[i2]) i2 = e;
        }
        float e2 = expf(noisy[i2] - noisy[i1]);
        float inv = 1.0f / (1.0f + e2);
        int s1 = atomicAdd(&g_counts[i1], 1);
        g_ptoken[i1 * TOK + s1] = gwarp;
        g_pgate [i1 * TOK + s1] = inv;
        int s2 = atomicAdd(&g_counts[i2], 1);
        g_ptoken[i2 * TOK + s2] = gwarp;
        g_pgate [i2 * TOK + s2] = e2 * inv;
        g_tslot[2 * gwarp]     = i1 * TOK + s1;
        g_tslot[2 * gwarp + 1] = i2 * TOK + s2;
    }

    __syncthreads();
    __threadfence();
    if (threadIdx.x == 0) {
        int t = atomicAdd(&g_done, 1);
        if (t == (int)gridDim.x - 1) {
            int s = 0;
#pragma unroll
            for (int e = 0; e < NE; e++) { g_offs[e] = s; s += g_counts[e]; }
        }
    }
}

// ---------------------------------------------------------------------------
// Launch 3: gather + fp16 hi/lo split of activations
// ---------------------------------------------------------------------------
__global__ void gather_kernel(const float* __restrict__ x) {
    int e    = blockIdx.x >> 13;
    int slot = blockIdx.x & (TOK - 1);
    if (slot >= g_counts[e]) return;
    int token = g_ptoken[e * TOK + slot];
    int p     = g_offs[e] + slot;

    float4 v = ((const float4*)(x + (size_t)token * DIM))[threadIdx.x];
    __half hx, lx, hy, ly, hz, lz, hw, lw;
    split_fp16(v.x, hx, lx); split_fp16(v.y, hy, ly);
    split_fp16(v.z, hz, lz); split_fp16(v.w, hw, lw);
    size_t o = (size_t)p * DIM + (size_t)threadIdx.x * 4;
    *(__half2*)&g_Xf[o]     = __halves2half2(hx, hy);
    *(__half2*)&g_Xf[o + 2] = __halves2half2(hz, hw);
    *(__half2*)&g_Xe[o]     = __halves2half2(lx, ly);
    *(__half2*)&g_Xe[o + 2] = __halves2half2(lz, lw);

    if (threadIdx.x == 0) g_cgate[p] = g_pgate[e * TOK + slot];
}

// ---------------------------------------------------------------------------
// GEMM tiling constants (R7 geometry, fp16 2-term tiles)
// ---------------------------------------------------------------------------
#define ROWB     80
#define A_BYTES  (128 * ROWB)   // 10240
#define B_BYTES  (64 * ROWB)    // 5120

#define G1_STAGE (2 * A_BYTES + 2 * B_BYTES)  // 30720  (Af, Ae, B1f, B3f)
#define G1_SMEM  (2 * G1_STAGE)               // 61440
#define G2_STAGE (2 * A_BYTES + 1 * B_BYTES)  // 25600  (Af, Ae, Bf)
#define G2_SMEM  (2 * G2_STAGE)               // 51200

// ---------------------------------------------------------------------------
// Launch 4: GEMM1 — G = swiglu(X @ w1^T, X @ w3^T), fp16 2-term split
// block 128x64(per matrix), BK=32, 8 warps (4x2), warp 32x32, occupancy 2
// ---------------------------------------------------------------------------
__global__ void __launch_bounds__(256, 2) gemm1_mma() {
    int e   = blockIdx.z;
    int cnt = g_counts[e];
    int m0  = blockIdx.y * 128;
    if (m0 >= cnt) return;
    int base = g_offs[e];
    int n0   = blockIdx.x * 64;

    extern __shared__ char smem[];
    uint32_t sb = smem_u32(smem);
    int tid = threadIdx.x, lane = tid & 31, wid = tid >> 5;
    int wm = wid >> 1, wn = wid & 1;
    int rl = cnt - m0; if (rl > 128) rl = 128;

    const __half* Af  = g_Xf  + (size_t)(base + m0) * DIM;
    const __half* Ae  = g_Xe  + (size_t)(base + m0) * DIM;
    const __half* B1f = g_w1f + ((size_t)e * HID + n0) * DIM;
    const __half* B3f = g_w3f + ((size_t)e * HID + n0) * DIM;

    auto load_stage = [&](int ci, int buf) {
        uint32_t s = sb + buf * G1_STAGE;
        int k0 = ci * 32;
#pragma unroll
        for (int it = 0; it < 2; it++) {
            int id = it * 256 + tid;
            int r = id >> 2, c = id & 3;
            int sz = (r < rl) ? 16 : 0;
            size_t go = (size_t)r * DIM + k0 + c * 8;
            uint32_t so = (uint32_t)(r * ROWB + c * 16);
            CP_ASYNC16(s + so,           Af + go, sz);
            CP_ASYNC16(s + A_BYTES + so, Ae + go, sz);
        }
        {
            int r = tid >> 2, c = tid & 3;
            size_t go = (size_t)r * DIM + k0 + c * 8;
            uint32_t so = (uint32_t)(r * ROWB + c * 16);
            uint32_t bb = s + 2 * A_BYTES;
            CP_ASYNC16(bb + so,           B1f + go, 16);
            CP_ASYNC16(bb + B_BYTES + so, B3f + go, 16);
        }
        CP_COMMIT();
    };

    float acc[2][2][4][4];
#pragma unroll
    for (int a = 0; a < 2; a++)
#pragma unroll
        for (int b = 0; b < 2; b++)
#pragma unroll
            for (int c = 0; c < 4; c++)
#pragma unroll
                for (int d = 0; d < 4; d++) acc[a][b][c][d] = 0.0f;

    uint32_t aRow  = (uint32_t)(lane & 15);
    uint32_t aHalf = (uint32_t)((lane >> 4) * 16);
    int g = lane >> 3;
    uint32_t bRowOff = (uint32_t)((((g >> 1) * 8) + (lane & 7)) * ROWB);
    uint32_t bKOff   = (uint32_t)((g & 1) * 16);

    load_stage(0, 0);
    for (int ci = 0; ci < 32; ci++) {
        int b = ci & 1;
        if (ci + 1 < 32) { load_stage(ci + 1, b ^ 1); CP_WAIT1(); }
        else             { CP_WAIT0(); }
        __syncthreads();
        uint32_t s = sb + b * G1_STAGE;
#pragma unroll
        for (int ks = 0; ks < 2; ks++) {
            uint32_t kb = (uint32_t)(ks * 32);
            uint32_t aF[2][4], aE[2][4];
#pragma unroll
            for (int mf = 0; mf < 2; mf++) {
                uint32_t ad = s + (uint32_t)((wm * 32 + mf * 16 + aRow) * ROWB) + kb + aHalf;
                ldsm4(aF[mf], ad);
                ldsm4(aE[mf], ad + A_BYTES);
            }
            uint32_t bb = s + 2 * A_BYTES;
#pragma unroll
            for (int nh = 0; nh < 2; nh++) {
                uint32_t bd = bb + (uint32_t)((wn * 32 + nh * 16) * ROWB) + bRowOff + kb + bKOff;
                uint32_t b1[4], b3[4];
                ldsm4(b1, bd);
                ldsm4(b3, bd + B_BYTES);
#pragma unroll
                for (int mf = 0; mf < 2; mf++)
#pragma unroll
                    for (int j = 0; j < 2; j++) {
                        int nf = nh * 2 + j;
                        mma16816(acc[0][mf][nf], aF[mf], &b1[j * 2]);
                        mma16816(acc[0][mf][nf], aE[mf], &b1[j * 2]);
                        mma16816(acc[1][mf][nf], aF[mf], &b3[j * 2]);
                        mma16816(acc[1][mf][nf], aE[mf], &b3[j * 2]);
                    }
            }
        }
        __syncthreads();
    }

    // Epilogue: swiglu, split, store fp16 hi/lo
#pragma unroll
    for (int mf = 0; mf < 2; mf++) {
#pragma unroll
        for (int nf = 0; nf < 4; nf++) {
            int r   = wm * 32 + mf * 16 + (lane >> 2);
            int col = n0 + wn * 32 + nf * 8 + (lane & 3) * 2;
#pragma unroll
            for (int half = 0; half < 2; half++) {
                int row = r + half * 8;
                if (row < rl) {
                    float h0 = acc[0][mf][nf][half * 2];
                    float h1 = acc[0][mf][nf][half * 2 + 1];
                    float x0 = acc[1][mf][nf][half * 2];
                    float x1 = acc[1][mf][nf][half * 2 + 1];
                    float v0 = h0 * (1.0f / (1.0f + __expf(-h0))) * x0;
                    float v1 = h1 * (1.0f / (1.0f + __expf(-h1))) * x1;
                    __half vh0, vl0, vh1, vl1;
                    split_fp16(v0, vh0, vl0);
                    split_fp16(v1, vh1, vl1);
                    size_t o = (size_t)(base + m0 + row) * HID + col;
                    *(__half2*)&g_Gf[o] = __halves2half2(vh0, vh1);
                    *(__half2*)&g_Ge[o] = __halves2half2(vl0, vl1);
                }
            }
        }
    }
}

// ---------------------------------------------------------------------------
// Launch 5: GEMM2 — Y[p] = gate[p] * (G[p] @ w2^T), fp16 2-term split
// ---------------------------------------------------------------------------
__global__ void __launch_bounds__(256, 2) gemm2_mma() {
    int e   = blockIdx.z;
    int cnt = g_counts[e];
    int m0  = blockIdx.y * 128;
    if (m0 >= cnt) return;
    int base = g_offs[e];
    int n0   = blockIdx.x * 64;

    extern __shared__ char smem[];
    uint32_t sb = smem_u32(smem);
    int tid = threadIdx.x, lane = tid & 31, wid = tid >> 5;
    int wm = wid >> 1, wn = wid & 1;
    int rl = cnt - m0; if (rl > 128) rl = 128;

    const __half* Af = g_Gf  + (size_t)(base + m0) * HID;
    const __half* Ae = g_Ge  + (size_t)(base + m0) * HID;
    const __half* Bf = g_w2f + ((size_t)e * DIM + n0) * HID;

    auto load_stage = [&](int ci, int buf) {
        uint32_t s = sb + buf * G2_STAGE;
        int k0 = ci * 32;
#pragma unroll
        for (int it = 0; it < 2; it++) {
            int id = it * 256 + tid;
            int r = id >> 2, c = id & 3;
            int sz = (r < rl) ? 16 : 0;
            size_t go = (size_t)r * HID + k0 + c * 8;
            uint32_t so = (uint32_t)(r * ROWB + c * 16);
            CP_ASYNC16(s + so,           Af + go, sz);
            CP_ASYNC16(s + A_BYTES + so, Ae + go, sz);
        }
        {
            int r = tid >> 2, c = tid & 3;
            size_t go = (size_t)r * HID + k0 + c * 8;
            uint32_t so = (uint32_t)(r * ROWB + c * 16);
            CP_ASYNC16(s + 2 * A_BYTES + so, Bf + go, 16);
        }
        CP_COMMIT();
    };

    float acc[2][4][4];
#pragma unroll
    for (int a = 0; a < 2; a++)
#pragma unroll
        for (int c = 0; c < 4; c++)
#pragma unroll
            for (int d = 0; d < 4; d++) acc[a][c][d] = 0.0f;

    uint32_t aRow  = (uint32_t)(lane & 15);
    uint32_t aHalf = (uint32_t)((lane >> 4) * 16);
    int g = lane >> 3;
    uint32_t bRowOff = (uint32_t)((((g >> 1) * 8) + (lane & 7)) * ROWB);
    uint32_t bKOff   = (uint32_t)((g & 1) * 16);

    load_stage(0, 0);
    for (int ci = 0; ci < 64; ci++) {
        int b = ci & 1;
        if (ci + 1 < 64) { load_stage(ci + 1, b ^ 1); CP_WAIT1(); }
        else             { CP_WAIT0(); }
        __syncthreads();
        uint32_t s = sb + b * G2_STAGE;
#pragma unroll
        for (int ks = 0; ks < 2; ks++) {
            uint32_t kb = (uint32_t)(ks * 32);
            uint32_t aF[2][4], aE[2][4];
#pragma unroll
            for (int mf = 0; mf < 2; mf++) {
                uint32_t ad = s + (uint32_t)((wm * 32 + mf * 16 + aRow) * ROWB) + kb + aHalf;
                ldsm4(aF[mf], ad);
                ldsm4(aE[mf], ad + A_BYTES);
            }
            uint32_t bb = s + 2 * A_BYTES;
#pragma unroll
            for (int nh = 0; nh < 2; nh++) {
                uint32_t bd = bb + (uint32_t)((wn * 32 + nh * 16) * ROWB) + bRowOff + kb + bKOff;
                uint32_t bf[4];
                ldsm4(bf, bd);
#pragma unroll
                for (int mf = 0; mf < 2; mf++)
#pragma unroll
                    for (int j = 0; j < 2; j++) {
                        int nf = nh * 2 + j;
                        mma16816(acc[mf][nf], aF[mf], &bf[j * 2]);
                        mma16816(acc[mf][nf], aE[mf], &bf[j * 2]);
                    }
            }
        }
        __syncthreads();
    }

    // Epilogue: gate-scale, store fp32 rows of Y
#pragma unroll
    for (int mf = 0; mf < 2; mf++) {
#pragma unroll
        for (int nf = 0; nf < 4; nf++) {
            int r   = wm * 32 + mf * 16 + (lane >> 2);
            int col = n0 + wn * 32 + nf * 8 + (lane & 3) * 2;
#pragma unroll
            for (int half = 0; half < 2; half++) {
                int row = r + half * 8;
                if (row < rl) {
                    float gate = g_cgate[base + m0 + row];
                    float2 v;
                    v.x = gate * acc[mf][nf][half * 2];
                    v.y = gate * acc[mf][nf][half * 2 + 1];
                    *(float2*)&g_Y[(size_t)(base + m0 + row) * DIM + col] = v;
                }
            }
        }
    }
}

// ---------------------------------------------------------------------------
// Launch 6: combine — out[token] = Y[pair0] + Y[pair1]
// ---------------------------------------------------------------------------
__global__ void combine_kernel(float* __restrict__ out) {
    int t = blockIdx.x;
    int e0 = g_tslot[2 * t], e1 = g_tslot[2 * t + 1];
    int p0 = g_offs[e0 >> 13] + (e0 & (TOK - 1));
    int p1 = g_offs[e1 >> 13] + (e1 & (TOK - 1));
    float4 a = ((const float4*)(g_Y + (size_t)p0 * DIM))[threadIdx.x];
    float4 b = ((const float4*)(g_Y + (size_t)p1 * DIM))[threadIdx.x];
    float4 r = make_float4(a.x + b.x, a.y + b.y, a.z + b.z, a.w + b.w);
    ((float4*)(out + (size_t)t * DIM))[threadIdx.x] = r;
}

// ---------------------------------------------------------------------------
// Launch
// ---------------------------------------------------------------------------
extern "C" void kernel_launch(void* const* d_in, const int* in_sizes, int n_in,
                              void* d_out, int out_size)
{
    const float* x     = (const float*)d_in[0];
    const float* noise = (const float*)d_in[1];
    const float* rw    = (const float*)d_in[2];
    const float* rb    = (const float*)d_in[3];
    const float* nw    = (const float*)d_in[4];
    const float* nb    = (const float*)d_in[5];
    const float* w1    = (const float*)d_in[6];
    const float* w2    = (const float*)d_in[7];
    const float* w3    = (const float*)d_in[8];
    float* out = (float*)d_out;

    cudaFuncSetAttribute(gemm1_mma, cudaFuncAttributeMaxDynamicSharedMemorySize, G1_SMEM);
    cudaFuncSetAttribute(gemm2_mma, cudaFuncAttributeMaxDynamicSharedMemorySize, G2_SMEM);

    const int n4 = (NE * HID * DIM) / 4;

    convert_kernel<<<3 * (n4 / 256), 256>>>(w1, w2, w3, n4);          // 1 (zeros counts+done)
    router_kernel<<<TOK / 8, 256>>>(x, noise, rw, rb, nw, nb);        // 2 (+ tail scan)
    gather_kernel<<<NE * TOK, 256>>>(x);                              // 3
    gemm1_mma<<<dim3(HID / 64, TOK / 128, NE), 256, G1_SMEM>>>();     // 4 <- ncu capture slot
    gemm2_mma<<<dim3(DIM / 64, TOK / 128, NE), 256, G2_SMEM>>>();     // 5
    combine_kernel<<<TOK, 256>>>(out);                                // 6
}